// round 6
// baseline (speedup 1.0000x reference)
#include <cuda_runtime.h>
#include <cuda_bf16.h>
#include <cstdint>
#include <cstddef>

typedef __nv_bfloat16 bf16;

#define BB   1024
#define CIN  256
#define HH   512
#define TT   32
#define EE   512
#define NEC  8192
#define RECON_N (BB*CIN*TT)
#define NNC  (BB*TT)          // 32768 GEMM-N for convs

// tile: BM=128, BN=256, BK=32, 8 warps (warp tile 64x64), double buffer
// per buf: Ah 10240 + Al 10240 + Bh 20480 + Bl 20480 = 61440
#define GS 122880

// ---------------- static device scratch ----------------
__device__ bf16 g_actAh[(size_t)NNC*HH], g_actAl[(size_t)NNC*HH];
__device__ bf16 g_actBh[(size_t)NNC*HH], g_actBl[(size_t)NNC*HH];
__device__ bf16 g_wA1h[512*768],   g_wA1l[512*768];
__device__ bf16 g_wA2h[512*1536],  g_wA2l[512*1536];
__device__ bf16 g_wA3h[512*1536],  g_wA3l[512*1536];
__device__ bf16 g_wA4h[512*1536],  g_wA4l[512*1536];
__device__ bf16 g_wD4h[512*1536],  g_wD4l[512*1536];
__device__ bf16 g_wD3h[512*1536],  g_wD3l[512*1536];
__device__ bf16 g_wD2h[512*1536],  g_wD2l[512*1536];
__device__ bf16 g_wD1h[256*1536],  g_wD1l[256*1536];
__device__ bf16 g_wFEh[(size_t)512*16384], g_wFEl[(size_t)512*16384];
__device__ bf16 g_wFDh[(size_t)16384*512], g_wFDl[(size_t)16384*512];
__device__ bf16 g_cbh[(size_t)NEC*EE],     g_cbl[(size_t)NEC*EE];
__device__ float g_dfb2[16384];
__device__ float g_part[(size_t)8*BB*EE];
__device__ float g_z[(size_t)BB*EE];
__device__ bf16  g_zh[(size_t)BB*EE],  g_zl[(size_t)BB*EE];
__device__ bf16  g_zqh[(size_t)BB*EE], g_zql[(size_t)BB*EE];
__device__ float g_dot[(size_t)BB*NEC];
__device__ float g_cn[NEC];
__device__ float g_lp[BB];

// ---------------- helpers ----------------
__device__ __forceinline__ void split2(float v, bf16& h, bf16& l){
    h = __float2bfloat16_rn(v);
    l = __float2bfloat16_rn(v - __bfloat162float(h));
}
__device__ __forceinline__ void mma_bf16(float* c, const uint32_t* a, const uint32_t* b){
    asm volatile("mma.sync.aligned.m16n8k16.row.col.f32.bf16.bf16.f32 "
        "{%0,%1,%2,%3}, {%4,%5,%6,%7}, {%8,%9}, {%0,%1,%2,%3};"
        : "+f"(c[0]), "+f"(c[1]), "+f"(c[2]), "+f"(c[3])
        : "r"(a[0]), "r"(a[1]), "r"(a[2]), "r"(a[3]), "r"(b[0]), "r"(b[1]));
}
__device__ __forceinline__ void ldsm4(uint32_t* r, uint32_t addr){
    asm volatile("ldmatrix.sync.aligned.m8n8.x4.shared.b16 {%0,%1,%2,%3}, [%4];"
        : "=r"(r[0]), "=r"(r[1]), "=r"(r[2]), "=r"(r[3]) : "r"(addr));
}
template<int N> __device__ __forceinline__ void cp_wait(){
    asm volatile("cp.async.wait_group %0;" :: "n"(N) : "memory");
}
__device__ __forceinline__ void cp_commit(){
    asm volatile("cp.async.commit_group;" ::: "memory");
}

// stage one (128 A rows + 256 B rows) x 32k chunk, hi+lo, via cp.async
__device__ __forceinline__ void stage_chunk(
    uint32_t sbU, int buf,
    const bf16* __restrict__ Ah, const bf16* __restrict__ Al,
    const bf16* __restrict__ Bh, const bf16* __restrict__ Bl,
    int m0, int n0, int k0, int K, int convC, int tid)
{
    uint32_t sb = sbU + buf*61440;
    #pragma unroll
    for (int half = 0; half < 2; half++){
        const bf16* src = half ? Al : Ah;
        uint32_t tb = sb + half*10240;
        #pragma unroll
        for (int it = 0; it < 2; it++){
            int task = tid + it*256;            // 512 = 128 rows x 4 segs
            int r = task >> 2, seg = task & 3;
            const void* g = src + (size_t)(m0 + r)*K + k0 + seg*8;
            asm volatile("cp.async.cg.shared.global [%0], [%1], 16;"
                :: "r"(tb + r*80 + seg*16), "l"(g));
        }
    }
    #pragma unroll
    for (int half = 0; half < 2; half++){
        const bf16* src = half ? Bl : Bh;
        uint32_t tb = sb + 20480 + half*20480;
        #pragma unroll
        for (int it = 0; it < 4; it++){
            int task = tid + it*256;            // 1024 = 256 rows x 4 segs
            int r = task >> 2, seg = task & 3;
            int n = n0 + r;
            const bf16* g; int sz = 16;
            if (convC){
                int t = n & 31, ks2 = k0 / convC, kr = k0 - ks2*convC;
                if ((unsigned)(t + ks2 - 1) < 32u)
                    g = src + (size_t)(n + ks2 - 1)*convC + kr + seg*8;
                else { g = src; sz = 0; }
            } else {
                g = src + (size_t)n*K + k0 + seg*8;
            }
            asm volatile("cp.async.cg.shared.global [%0], [%1], 16, %2;"
                :: "r"(tb + r*80 + seg*16), "l"((const void*)g), "r"(sz));
        }
    }
}

// =====================================================================
// split-bf16 NT GEMM via mma.sync + ldmatrix.
// grid = (Ntot/256, Mtot/128, zsplit). convC: implicit im2col on B rows.
// fmode 1 -> outF[n*ldc+m]; fmode 2 -> outF[(n>>5)*Mtot*32+m*32+(n&31)];
// outH/outL -> split act at [n*Mtot+m]. zsplit>1: fp32 partials.
// =====================================================================
__global__ void __launch_bounds__(256, 1) gemm_mma(
    const bf16* __restrict__ Ah, const bf16* __restrict__ Al,
    const bf16* __restrict__ Bh, const bf16* __restrict__ Bl,
    const float* __restrict__ bias, float* __restrict__ outF,
    bf16* __restrict__ outH, bf16* __restrict__ outL,
    float* __restrict__ partBase,
    int Mtot, int K, int kseg, int convC, int fmode, int ldc, int relu)
{
    extern __shared__ char smem[];
    const uint32_t sbU = (uint32_t)__cvta_generic_to_shared(smem);
    const int tid  = threadIdx.x;
    const int lane = tid & 31, wid = tid >> 5;
    const int wm = wid >> 2, wn = wid & 3;     // 2 x 4 warps, 64x64 each
    const int m0 = blockIdx.y * 128;
    const int n0 = blockIdx.x * 256;
    const int kb = blockIdx.z * kseg;
    const int NC = kseg / 32;

    float acc[4][8][4];
    #pragma unroll
    for (int i = 0; i < 4; i++)
        #pragma unroll
        for (int j = 0; j < 8; j++)
            #pragma unroll
            for (int r = 0; r < 4; r++) acc[i][j][r] = 0.f;

    stage_chunk(sbU, 0, Ah, Al, Bh, Bl, m0, n0, kb, K, convC, tid);
    cp_commit();
    if (NC > 1){
        stage_chunk(sbU, 1, Ah, Al, Bh, Bl, m0, n0, kb + 32, K, convC, tid);
        cp_commit();
    }

    // ldmatrix base offsets (per-thread row mapping)
    const int lrow = lane & 15, lk = (lane >> 4) * 16;

    for (int ci = 0; ci < NC; ci++){
        if (ci + 1 < NC) cp_wait<1>(); else cp_wait<0>();
        __syncthreads();

        const uint32_t sb = sbU + (ci & 1) * 61440;
        const uint32_t aBase = sb + (uint32_t)(wm*64 + lrow)*80 + lk;
        const uint32_t bBase = sb + 20480 + (uint32_t)(wn*64 + lrow)*80 + lk;

        #pragma unroll
        for (int s = 0; s < 2; s++){
            const uint32_t ko = s*32;
            uint32_t ah[4][4], al[4][4], bh[8][2], bl[8][2];
            #pragma unroll
            for (int i = 0; i < 4; i++){
                ldsm4(ah[i], aBase + i*1280 + ko);
                ldsm4(al[i], aBase + 10240 + i*1280 + ko);
            }
            #pragma unroll
            for (int jp = 0; jp < 4; jp++){
                uint32_t r[4];
                ldsm4(r, bBase + jp*1280 + ko);
                bh[2*jp][0] = r[0]; bh[2*jp+1][0] = r[1];
                bh[2*jp][1] = r[2]; bh[2*jp+1][1] = r[3];
                ldsm4(r, bBase + 20480 + jp*1280 + ko);
                bl[2*jp][0] = r[0]; bl[2*jp+1][0] = r[1];
                bl[2*jp][1] = r[2]; bl[2*jp+1][1] = r[3];
            }
            #pragma unroll
            for (int i = 0; i < 4; i++)
                #pragma unroll
                for (int j = 0; j < 8; j++){
                    mma_bf16(acc[i][j], ah[i], bh[j]);
                    mma_bf16(acc[i][j], ah[i], bl[j]);
                    mma_bf16(acc[i][j], al[i], bh[j]);
                }
        }
        __syncthreads();
        if (ci + 2 < NC){
            stage_chunk(sbU, ci & 1, Ah, Al, Bh, Bl, m0, n0,
                        kb + (ci + 2)*32, K, convC, tid);
            cp_commit();
        }
    }

    // ---- epilogue ----
    const bool dosplit = (gridDim.z > 1);
    const int nTot = gridDim.x * 256;
    float* fO = outF; int fm = fmode; int lld = ldc;
    bf16 *oH = outH, *oL = outL;
    if (dosplit){
        fO = partBase + (size_t)blockIdx.z * Mtot * nTot;
        fm = 1; lld = Mtot; oH = nullptr; oL = nullptr;
    }
    #pragma unroll
    for (int i = 0; i < 4; i++){
        const int mA = m0 + wm*64 + i*16 + (lane >> 2);
        const int mB = mA + 8;
        const float bvA = (!dosplit && bias) ? bias[mA] : 0.f;
        const float bvB = (!dosplit && bias) ? bias[mB] : 0.f;
        #pragma unroll
        for (int j = 0; j < 8; j++){
            const int nb = n0 + wn*64 + j*8 + (lane & 3)*2;
            float v[4];
            v[0] = acc[i][j][0] + bvA;  v[1] = acc[i][j][1] + bvA;
            v[2] = acc[i][j][2] + bvB;  v[3] = acc[i][j][3] + bvB;
            if (relu){
                #pragma unroll
                for (int r = 0; r < 4; r++) v[r] = fmaxf(v[r], 0.f);
            }
            const int mm[4] = {mA, mA, mB, mB};
            const int nn[4] = {nb, nb + 1, nb, nb + 1};
            #pragma unroll
            for (int r = 0; r < 4; r++){
                const int m = mm[r], n = nn[r];
                if (fm == 1)
                    fO[(size_t)n * lld + m] = v[r];
                else if (fm == 2)
                    fO[(size_t)(n >> 5) * ((size_t)Mtot * 32) + (size_t)m * 32 + (n & 31)] = v[r];
                if (oH){
                    bf16 h = __float2bfloat16_rn(v[r]);
                    oH[(size_t)n * Mtot + m] = h;
                    oL[(size_t)n * Mtot + m] = __float2bfloat16_rn(v[r] - __bfloat162float(h));
                }
            }
        }
    }
}

// ---------------- transforms ----------------
__global__ __launch_bounds__(256) void wconv_k(const float* __restrict__ w,
    bf16* __restrict__ h, bf16* __restrict__ l, int O, int C, int isT)
{
    int total = O * C * 3;
    for (int i = blockIdx.x*blockDim.x + threadIdx.x; i < total; i += gridDim.x*blockDim.x){
        int o = i / (C*3), r = i % (C*3), c = r / 3, k = r % 3;
        float v = isT ? w[((size_t)c*O + o)*3 + (2 - k)] : w[i];
        size_t d = (size_t)o*(3*C) + k*C + c;
        bf16 hh, ll; split2(v, hh, ll); h[d] = hh; l[d] = ll;
    }
}
__global__ __launch_bounds__(256) void wfe_k(const float* __restrict__ w,
    bf16* __restrict__ h, bf16* __restrict__ l)
{
    size_t total = (size_t)512*16384;
    for (size_t i = blockIdx.x*(size_t)blockDim.x + threadIdx.x; i < total;
         i += (size_t)gridDim.x*blockDim.x){
        int e = (int)(i >> 14), fp = (int)(i & 16383);
        int t = fp >> 9, c = fp & 511;
        float v = w[(size_t)e*16384 + c*32 + t];
        bf16 hh, ll; split2(v, hh, ll); h[i] = hh; l[i] = ll;
    }
}
__global__ __launch_bounds__(256) void wfd_k(const float* __restrict__ w,
    bf16* __restrict__ h, bf16* __restrict__ l)
{
    size_t total = (size_t)16384*512;
    for (size_t i = blockIdx.x*(size_t)blockDim.x + threadIdx.x; i < total;
         i += (size_t)gridDim.x*blockDim.x){
        int fp = (int)(i >> 9), e = (int)(i & 511);
        int t = fp >> 9, c = fp & 511;
        float v = w[((size_t)(c*32 + t))*512 + e];
        bf16 hh, ll; split2(v, hh, ll); h[i] = hh; l[i] = ll;
    }
}
__global__ __launch_bounds__(256) void dfb2_k(const float* __restrict__ b,
    float* __restrict__ b2)
{
    int i = blockIdx.x*blockDim.x + threadIdx.x;
    int t = i >> 9, c = i & 511;
    b2[i] = b[c*32 + t];
}
__global__ __launch_bounds__(256) void plainsplit_k(const float* __restrict__ s,
    bf16* __restrict__ h, bf16* __restrict__ l, size_t n)
{
    for (size_t i = blockIdx.x*(size_t)blockDim.x + threadIdx.x; i < n;
         i += (size_t)gridDim.x*blockDim.x){
        bf16 hh, ll; split2(s[i], hh, ll); h[i] = hh; l[i] = ll;
    }
}
__global__ __launch_bounds__(256) void xsplit_k(const float* __restrict__ x,
    bf16* __restrict__ h, bf16* __restrict__ l)
{
    size_t total = (size_t)BB*CIN*TT;
    for (size_t i = blockIdx.x*(size_t)blockDim.x + threadIdx.x; i < total;
         i += (size_t)gridDim.x*blockDim.x){
        int b = (int)(i >> 13), r = (int)(i & 8191);
        int c = r >> 5, t = r & 31;
        size_t d = (size_t)(b*32 + t)*256 + c;
        bf16 hh, ll; split2(x[i], hh, ll); h[d] = hh; l[d] = ll;
    }
}
__global__ __launch_bounds__(256) void reducez_k(const float* __restrict__ part,
    const float* __restrict__ efb, float* __restrict__ z,
    bf16* __restrict__ zh, bf16* __restrict__ zl)
{
    int i = blockIdx.x*blockDim.x + threadIdx.x;   // 524288
    int e = i & 511;
    float s = 0.f;
    #pragma unroll
    for (int k = 0; k < 8; k++) s += part[(size_t)k*524288 + i];
    s += efb[e];
    z[i] = s;
    bf16 hh, ll; split2(s, hh, ll); zh[i] = hh; zl[i] = ll;
}
__global__ __launch_bounds__(256) void cnorm_k(const float* __restrict__ cb,
                                               float* __restrict__ cn)
{
    int n = blockIdx.x*8 + (threadIdx.x >> 5);
    int lane = threadIdx.x & 31;
    const float* r = cb + (size_t)n*EE;
    float s = 0.f;
    for (int e = lane; e < EE; e += 32){ float v = r[e]; s += v*v; }
    #pragma unroll
    for (int o = 16; o; o >>= 1) s += __shfl_down_sync(0xffffffffu, s, o);
    if (lane == 0) cn[n] = s;
}
__global__ __launch_bounds__(256) void vq_k(
    const float* __restrict__ z, const float* __restrict__ dot,
    const float* __restrict__ cn, const float* __restrict__ cb,
    bf16* __restrict__ zqh, bf16* __restrict__ zql, float* __restrict__ lp)
{
    __shared__ float sv[256];
    __shared__ int   si[256];
    __shared__ float s_zn;
    const int b = blockIdx.x, tid = threadIdx.x;
    const float* zb = z + (size_t)b*EE;

    float zn = 0.f;
    for (int e = tid; e < EE; e += 256){ float v = zb[e]; zn += v*v; }
    sv[tid] = zn; __syncthreads();
    for (int s = 128; s > 0; s >>= 1){ if (tid < s) sv[tid] += sv[tid+s]; __syncthreads(); }
    if (tid == 0) s_zn = sv[0];
    __syncthreads();
    zn = s_zn; __syncthreads();

    const float* db = dot + (size_t)b*NEC;
    float best = 3.4e38f; int bi = 0x7fffffff;
    for (int n = tid; n < NEC; n += 256){
        float dv = (zn + cn[n]) - 2.0f * db[n];
        if (dv < best || (dv == best && n < bi)){ best = dv; bi = n; }
    }
    sv[tid] = best; si[tid] = bi; __syncthreads();
    for (int s = 128; s > 0; s >>= 1){
        if (tid < s){
            float v2 = sv[tid+s]; int i2 = si[tid+s];
            if (v2 < sv[tid] || (v2 == sv[tid] && i2 < si[tid])){ sv[tid] = v2; si[tid] = i2; }
        }
        __syncthreads();
    }
    const int idx = si[0];
    __syncthreads();

    const float* cbr = cb + (size_t)idx*EE;
    float ls = 0.f;
    for (int e = tid; e < EE; e += 256){
        float q = cbr[e];
        bf16 hh, ll; split2(q, hh, ll);
        zqh[(size_t)b*EE + e] = hh; zql[(size_t)b*EE + e] = ll;
        float d = q - zb[e]; ls += d*d;
    }
    sv[tid] = ls; __syncthreads();
    for (int s = 128; s > 0; s >>= 1){ if (tid < s) sv[tid] += sv[tid+s]; __syncthreads(); }
    if (tid == 0) lp[b] = sv[0];
}
__global__ __launch_bounds__(256) void loss_final_k(const float* __restrict__ lp,
                                                    float* __restrict__ outLoss)
{
    __shared__ float sm[256];
    int tid = threadIdx.x;
    float s = 0.f;
    #pragma unroll
    for (int i = 0; i < 4; i++) s += lp[tid + i*256];
    sm[tid] = s; __syncthreads();
    for (int st = 128; st > 0; st >>= 1){ if (tid < st) sm[tid] += sm[tid+st]; __syncthreads(); }
    if (tid == 0) *outLoss = sm[0] * 1.25f / ((float)BB * (float)EE);
}

// =====================================================================
#define SYM(p, s) do{ void* _t; cudaGetSymbolAddress(&_t, s); p = (decltype(p))_t; }while(0)

extern "C" void kernel_launch(void* const* d_in, const int* in_sizes, int n_in,
                              void* d_out, int out_size)
{
    const float* x   = (const float*)d_in[0];
    const float* ew1 = (const float*)d_in[1];  const float* eb1 = (const float*)d_in[2];
    const float* ew2 = (const float*)d_in[3];  const float* eb2 = (const float*)d_in[4];
    const float* ew3 = (const float*)d_in[5];  const float* eb3 = (const float*)d_in[6];
    const float* ew4 = (const float*)d_in[7];  const float* eb4 = (const float*)d_in[8];
    const float* efw = (const float*)d_in[9];  const float* efb = (const float*)d_in[10];
    const float* cb  = (const float*)d_in[11];
    const float* dfw = (const float*)d_in[12]; const float* dfb = (const float*)d_in[13];
    const float* dw4 = (const float*)d_in[14]; const float* db4 = (const float*)d_in[15];
    const float* dw3 = (const float*)d_in[16]; const float* db3 = (const float*)d_in[17];
    const float* dw2 = (const float*)d_in[18]; const float* db2 = (const float*)d_in[19];
    const float* dw1 = (const float*)d_in[20]; const float* db1 = (const float*)d_in[21];
    float* out = (float*)d_out;

    bf16 *aAh,*aAl,*aBh,*aBl;
    bf16 *w1h,*w1l,*w2h,*w2l,*w3h,*w3l,*w4h,*w4l;
    bf16 *d4h,*d4l,*d3h,*d3l,*d2h,*d2l,*d1h,*d1l;
    bf16 *feh,*fel,*fdh,*fdl,*cbh,*cbl,*zh,*zl,*zqh,*zql;
    float *part,*z,*dot,*cn,*lp,*dfb2;
    SYM(aAh,g_actAh); SYM(aAl,g_actAl); SYM(aBh,g_actBh); SYM(aBl,g_actBl);
    SYM(w1h,g_wA1h); SYM(w1l,g_wA1l); SYM(w2h,g_wA2h); SYM(w2l,g_wA2l);
    SYM(w3h,g_wA3h); SYM(w3l,g_wA3l); SYM(w4h,g_wA4h); SYM(w4l,g_wA4l);
    SYM(d4h,g_wD4h); SYM(d4l,g_wD4l); SYM(d3h,g_wD3h); SYM(d3l,g_wD3l);
    SYM(d2h,g_wD2h); SYM(d2l,g_wD2l); SYM(d1h,g_wD1h); SYM(d1l,g_wD1l);
    SYM(feh,g_wFEh); SYM(fel,g_wFEl); SYM(fdh,g_wFDh); SYM(fdl,g_wFDl);
    SYM(cbh,g_cbh);  SYM(cbl,g_cbl);
    SYM(zh,g_zh); SYM(zl,g_zl); SYM(zqh,g_zqh); SYM(zql,g_zql);
    SYM(part,g_part); SYM(z,g_z); SYM(dot,g_dot); SYM(cn,g_cn); SYM(lp,g_lp);
    SYM(dfb2,g_dfb2);

    cudaFuncSetAttribute(gemm_mma, cudaFuncAttributeMaxDynamicSharedMemorySize, GS);

    // ---- transforms ----
    xsplit_k<<<1024, 256>>>(x, aAh, aAl);
    wconv_k<<<512, 256>>>(ew1, w1h, w1l, 512, 256, 0);
    wconv_k<<<512, 256>>>(ew2, w2h, w2l, 512, 512, 0);
    wconv_k<<<512, 256>>>(ew3, w3h, w3l, 512, 512, 0);
    wconv_k<<<512, 256>>>(ew4, w4h, w4l, 512, 512, 0);
    wfe_k<<<2048, 256>>>(efw, feh, fel);
    plainsplit_k<<<2048, 256>>>(cb, cbh, cbl, (size_t)NEC*EE);
    cnorm_k<<<NEC/8, 256>>>(cb, cn);
    wfd_k<<<2048, 256>>>(dfw, fdh, fdl);
    dfb2_k<<<64, 256>>>(dfb, dfb2);
    wconv_k<<<512, 256>>>(dw4, d4h, d4l, 512, 512, 1);
    wconv_k<<<512, 256>>>(dw3, d3h, d3l, 512, 512, 1);
    wconv_k<<<512, 256>>>(dw2, d2h, d2l, 512, 512, 1);
    wconv_k<<<512, 256>>>(dw1, d1h, d1l, 256, 512, 1);

    // ---- encoder convs ----
    gemm_mma<<<dim3(NNC/256, 4, 1), 256, GS>>>(w1h, w1l, aAh, aAl, eb1,
        nullptr, aBh, aBl, nullptr, 512, 768,  768,  256, 0, 0, 1);
    gemm_mma<<<dim3(NNC/256, 4, 1), 256, GS>>>(w2h, w2l, aBh, aBl, eb2,
        nullptr, aAh, aAl, nullptr, 512, 1536, 1536, 512, 0, 0, 1);
    gemm_mma<<<dim3(NNC/256, 4, 1), 256, GS>>>(w3h, w3l, aAh, aAl, eb3,
        nullptr, aBh, aBl, nullptr, 512, 1536, 1536, 512, 0, 0, 1);
    gemm_mma<<<dim3(NNC/256, 4, 1), 256, GS>>>(w4h, w4l, aBh, aBl, eb4,
        nullptr, aAh, aAl, nullptr, 512, 1536, 1536, 512, 0, 0, 1);

    // ---- encoder FC: M=512, N=1024, K=16384, split-K=8 ----
    gemm_mma<<<dim3(BB/256, 4, 8), 256, GS>>>(feh, fel, aAh, aAl, nullptr,
        nullptr, nullptr, nullptr, part, 512, 16384, 2048, 0, 0, 0, 0);
    reducez_k<<<2048, 256>>>(part, efb, z, zh, zl);

    // ---- VQ: dot = z @ cb^T ----
    gemm_mma<<<dim3(BB/256, NEC/128, 1), 256, GS>>>(cbh, cbl, zh, zl, nullptr,
        dot, nullptr, nullptr, nullptr, NEC, EE, EE, 0, 1, NEC, 0);
    vq_k<<<BB, 256>>>(z, dot, cn, cb, zqh, zql, lp);

    // ---- decoder FC: M=16384, N=1024, K=512 ----
    gemm_mma<<<dim3(BB/256, 16384/128, 1), 256, GS>>>(fdh, fdl, zqh, zql, dfb2,
        nullptr, aBh, aBl, nullptr, 16384, EE, EE, 0, 0, 0, 0);

    // ---- decoder convs ----
    gemm_mma<<<dim3(NNC/256, 4, 1), 256, GS>>>(d4h, d4l, aBh, aBl, db4,
        nullptr, aAh, aAl, nullptr, 512, 1536, 1536, 512, 0, 0, 1);
    gemm_mma<<<dim3(NNC/256, 4, 1), 256, GS>>>(d3h, d3l, aAh, aAl, db3,
        nullptr, aBh, aBl, nullptr, 512, 1536, 1536, 512, 0, 0, 1);
    gemm_mma<<<dim3(NNC/256, 4, 1), 256, GS>>>(d2h, d2l, aBh, aBl, db2,
        nullptr, aAh, aAl, nullptr, 512, 1536, 1536, 512, 0, 0, 1);
    gemm_mma<<<dim3(NNC/256, 2, 1), 256, GS>>>(d1h, d1l, aAh, aAl, db1,
        out, nullptr, nullptr, nullptr, 256, 1536, 1536, 512, 2, 0, 0);

    if (out_size >= RECON_N + 1)
        loss_final_k<<<1, 256>>>(lp, out + RECON_N);
}

// round 8
// speedup vs baseline: 1.3271x; 1.3271x over previous
#include <cuda_runtime.h>
#include <cuda_bf16.h>
#include <cstdint>
#include <cstddef>

typedef __nv_bfloat16 bf16;

#define BB   1024
#define CIN  256
#define HH   512
#define TT   32
#define EE   512
#define NEC  8192
#define RECON_N (BB*CIN*TT)
#define NNC  (BB*TT)          // 32768 GEMM-N for convs

#define GS 81920              // 2 buffers x 4 tiles x 10240B -> 2 CTAs/SM

// ---------------- static device scratch ----------------
__device__ bf16 g_actAh[(size_t)NNC*HH], g_actAl[(size_t)NNC*HH];
__device__ bf16 g_actBh[(size_t)NNC*HH], g_actBl[(size_t)NNC*HH];
__device__ bf16 g_wA1h[512*768],   g_wA1l[512*768];
__device__ bf16 g_wA2h[512*1536],  g_wA2l[512*1536];
__device__ bf16 g_wA3h[512*1536],  g_wA3l[512*1536];
__device__ bf16 g_wA4h[512*1536],  g_wA4l[512*1536];
__device__ bf16 g_wD4h[512*1536],  g_wD4l[512*1536];
__device__ bf16 g_wD3h[512*1536],  g_wD3l[512*1536];
__device__ bf16 g_wD2h[512*1536],  g_wD2l[512*1536];
__device__ bf16 g_wD1h[256*1536],  g_wD1l[256*1536];
__device__ bf16 g_wFEh[(size_t)512*16384], g_wFEl[(size_t)512*16384];
__device__ bf16 g_wFDh[(size_t)16384*512], g_wFDl[(size_t)16384*512];
__device__ bf16 g_cbh[(size_t)NEC*EE],     g_cbl[(size_t)NEC*EE];
__device__ float g_dfb2[16384];
__device__ float g_part[(size_t)8*BB*EE];
__device__ float g_z[(size_t)BB*EE];
__device__ bf16  g_zh[(size_t)BB*EE],  g_zl[(size_t)BB*EE];
__device__ bf16  g_zqh[(size_t)BB*EE], g_zql[(size_t)BB*EE];
__device__ float g_dot[(size_t)BB*NEC];
__device__ float g_cn[NEC];
__device__ float g_lp[BB];

// ---------------- helpers ----------------
__device__ __forceinline__ void split2(float v, bf16& h, bf16& l){
    h = __float2bfloat16_rn(v);
    l = __float2bfloat16_rn(v - __bfloat162float(h));
}
__device__ __forceinline__ void mma_bf16(float* c, const uint32_t* a, const uint32_t* b){
    asm volatile("mma.sync.aligned.m16n8k16.row.col.f32.bf16.bf16.f32 "
        "{%0,%1,%2,%3}, {%4,%5,%6,%7}, {%8,%9}, {%0,%1,%2,%3};"
        : "+f"(c[0]), "+f"(c[1]), "+f"(c[2]), "+f"(c[3])
        : "r"(a[0]), "r"(a[1]), "r"(a[2]), "r"(a[3]), "r"(b[0]), "r"(b[1]));
}
__device__ __forceinline__ void ldsm4(uint32_t* r, uint32_t addr){
    asm volatile("ldmatrix.sync.aligned.m8n8.x4.shared.b16 {%0,%1,%2,%3}, [%4];"
        : "=r"(r[0]), "=r"(r[1]), "=r"(r[2]), "=r"(r[3]) : "r"(addr));
}
template<int N> __device__ __forceinline__ void cp_wait(){
    asm volatile("cp.async.wait_group %0;" :: "n"(N) : "memory");
}
__device__ __forceinline__ void cp_commit(){
    asm volatile("cp.async.commit_group;" ::: "memory");
}

// stage one 128x32 x4-tile chunk into buffer `buf` via cp.async (16B, zfill for halo)
__device__ __forceinline__ void stage_chunk(
    uint32_t sbU, int buf,
    const bf16* __restrict__ Ah, const bf16* __restrict__ Al,
    const bf16* __restrict__ Bh, const bf16* __restrict__ Bl,
    int m0, int n0, int k0, int K, int convC, int tid)
{
    uint32_t sb = sbU + buf*40960;
    #pragma unroll
    for (int half = 0; half < 2; half++){
        const bf16* src = half ? Al : Ah;
        uint32_t tb = sb + half*10240;
        #pragma unroll
        for (int it = 0; it < 2; it++){
            int task = tid + it*256;
            int r = task >> 2, seg = task & 3;
            const void* g = src + (size_t)(m0 + r)*K + k0 + seg*8;
            asm volatile("cp.async.cg.shared.global [%0], [%1], 16;"
                :: "r"(tb + r*80 + seg*16), "l"(g));
        }
    }
    #pragma unroll
    for (int half = 0; half < 2; half++){
        const bf16* src = half ? Bl : Bh;
        uint32_t tb = sb + 20480 + half*10240;
        #pragma unroll
        for (int it = 0; it < 2; it++){
            int task = tid + it*256;
            int r = task >> 2, seg = task & 3;
            int n = n0 + r;
            const bf16* g; int sz = 16;
            if (convC){
                int t = n & 31, ks2 = k0 / convC, kr = k0 - ks2*convC;
                if ((unsigned)(t + ks2 - 1) < 32u)
                    g = src + (size_t)(n + ks2 - 1)*convC + kr + seg*8;
                else { g = src; sz = 0; }
            } else {
                g = src + (size_t)n*K + k0 + seg*8;
            }
            asm volatile("cp.async.cg.shared.global [%0], [%1], 16, %2;"
                :: "r"(tb + r*80 + seg*16), "l"((const void*)g), "r"(sz));
        }
    }
}

// =====================================================================
// split-bf16 NT GEMM via mma.sync + ldmatrix (R4 tile config).
// grid = (Ntot/128, Mtot/128, zsplit). convC: implicit im2col on B rows.
// fmode 1 -> outF[n*ldc+m]; fmode 2 -> outF[(n>>5)*Mtot*32+m*32+(n&31)];
// outH/outL -> split act at [n*Mtot+m]. zsplit>1: fp32 partials.
// =====================================================================
__global__ void __launch_bounds__(256) gemm_mma(
    const bf16* __restrict__ Ah, const bf16* __restrict__ Al,
    const bf16* __restrict__ Bh, const bf16* __restrict__ Bl,
    const float* __restrict__ bias, float* __restrict__ outF,
    bf16* __restrict__ outH, bf16* __restrict__ outL,
    float* __restrict__ partBase,
    int Mtot, int K, int kseg, int convC, int fmode, int ldc, int relu)
{
    extern __shared__ char smem[];
    const uint32_t sbU = (uint32_t)__cvta_generic_to_shared(smem);
    const int tid  = threadIdx.x;
    const int lane = tid & 31, wid = tid >> 5;
    const int wm = wid >> 2, wn = wid & 3;     // 2 x 4 warps, 64x32 each
    const int m0 = blockIdx.y * 128;
    const int n0 = blockIdx.x * 128;
    const int kb = blockIdx.z * kseg;
    const int NC = kseg / 32;

    float acc[4][4][4];
    #pragma unroll
    for (int i = 0; i < 4; i++)
        #pragma unroll
        for (int j = 0; j < 4; j++)
            #pragma unroll
            for (int r = 0; r < 4; r++) acc[i][j][r] = 0.f;

    stage_chunk(sbU, 0, Ah, Al, Bh, Bl, m0, n0, kb, K, convC, tid);
    cp_commit();
    if (NC > 1){
        stage_chunk(sbU, 1, Ah, Al, Bh, Bl, m0, n0, kb + 32, K, convC, tid);
        cp_commit();
    }

    const int lrow = lane & 15, lk2 = (lane >> 4) * 16;

    for (int ci = 0; ci < NC; ci++){
        if (ci + 1 < NC) cp_wait<1>(); else cp_wait<0>();
        __syncthreads();

        const uint32_t sb = sbU + (ci & 1) * 40960;
        const uint32_t aBase = sb + (uint32_t)(wm*64 + lrow)*80 + lk2;
        const uint32_t bBase = sb + 20480 + (uint32_t)(wn*32 + lrow)*80 + lk2;

        #pragma unroll
        for (int s = 0; s < 2; s++){
            const uint32_t ko = s*32;
            uint32_t ah[4][4], al[4][4], bh[4][2], bl[4][2];
            #pragma unroll
            for (int i = 0; i < 4; i++){
                ldsm4(ah[i], aBase + i*1280 + ko);
                ldsm4(al[i], aBase + 10240 + i*1280 + ko);
            }
            #pragma unroll
            for (int jp = 0; jp < 2; jp++){
                uint32_t r[4];
                ldsm4(r, bBase + jp*1280 + ko);
                bh[2*jp][0] = r[0]; bh[2*jp+1][0] = r[1];
                bh[2*jp][1] = r[2]; bh[2*jp+1][1] = r[3];
                ldsm4(r, bBase + 10240 + jp*1280 + ko);
                bl[2*jp][0] = r[0]; bl[2*jp+1][0] = r[1];
                bl[2*jp][1] = r[2]; bl[2*jp+1][1] = r[3];
            }
            #pragma unroll
            for (int i = 0; i < 4; i++)
                #pragma unroll
                for (int j = 0; j < 4; j++){
                    mma_bf16(acc[i][j], ah[i], bh[j]);
                    mma_bf16(acc[i][j], ah[i], bl[j]);
                    mma_bf16(acc[i][j], al[i], bh[j]);
                }
        }
        __syncthreads();
        if (ci + 2 < NC){
            stage_chunk(sbU, ci & 1, Ah, Al, Bh, Bl, m0, n0,
                        kb + (ci + 2)*32, K, convC, tid);
            cp_commit();
        }
    }

    // ---- epilogue ----
    const bool dosplit = (gridDim.z > 1);
    const int nTot = gridDim.x * 128;
    float* fO = outF; int fm = fmode; int lld = ldc;
    bf16 *oH = outH, *oL = outL;
    if (dosplit){
        fO = partBase + (size_t)blockIdx.z * Mtot * nTot;
        fm = 1; lld = Mtot; oH = nullptr; oL = nullptr;
    }
    #pragma unroll
    for (int i = 0; i < 4; i++){
        const int mA = m0 + wm*64 + i*16 + (lane >> 2);
        const int mB = mA + 8;
        const float bvA = (!dosplit && bias) ? bias[mA] : 0.f;
        const float bvB = (!dosplit && bias) ? bias[mB] : 0.f;
        #pragma unroll
        for (int j = 0; j < 4; j++){
            const int nb = n0 + wn*32 + j*8 + (lane & 3)*2;
            float v[4];
            v[0] = acc[i][j][0] + bvA;  v[1] = acc[i][j][1] + bvA;
            v[2] = acc[i][j][2] + bvB;  v[3] = acc[i][j][3] + bvB;
            if (relu){
                #pragma unroll
                for (int r = 0; r < 4; r++) v[r] = fmaxf(v[r], 0.f);
            }
            const int mm[4] = {mA, mA, mB, mB};
            const int nn[4] = {nb, nb + 1, nb, nb + 1};
            #pragma unroll
            for (int r = 0; r < 4; r++){
                const int m = mm[r], n = nn[r];
                if (fm == 1)
                    fO[(size_t)n * lld + m] = v[r];
                else if (fm == 2)
                    fO[(size_t)(n >> 5) * ((size_t)Mtot * 32) + (size_t)m * 32 + (n & 31)] = v[r];
                if (oH){
                    bf16 h = __float2bfloat16_rn(v[r]);
                    oH[(size_t)n * Mtot + m] = h;
                    oL[(size_t)n * Mtot + m] = __float2bfloat16_rn(v[r] - __bfloat162float(h));
                }
            }
        }
    }
}

// ---------------- transforms ----------------
__global__ __launch_bounds__(256) void wconv_k(const float* __restrict__ w,
    bf16* __restrict__ h, bf16* __restrict__ l, int O, int C, int isT)
{
    int total = O * C * 3;
    for (int i = blockIdx.x*blockDim.x + threadIdx.x; i < total; i += gridDim.x*blockDim.x){
        int o = i / (C*3), r = i % (C*3), c = r / 3, k = r % 3;
        float v = isT ? w[((size_t)c*O + o)*3 + (2 - k)] : w[i];
        size_t d = (size_t)o*(3*C) + k*C + c;
        bf16 hh, ll; split2(v, hh, ll); h[d] = hh; l[d] = ll;
    }
}
__global__ __launch_bounds__(256) void wfe_k(const float* __restrict__ w,
    bf16* __restrict__ h, bf16* __restrict__ l)
{
    size_t total = (size_t)512*16384;
    for (size_t i = blockIdx.x*(size_t)blockDim.x + threadIdx.x; i < total;
         i += (size_t)gridDim.x*blockDim.x){
        int e = (int)(i >> 14), fp = (int)(i & 16383);
        int t = fp >> 9, c = fp & 511;
        float v = w[(size_t)e*16384 + c*32 + t];
        bf16 hh, ll; split2(v, hh, ll); h[i] = hh; l[i] = ll;
    }
}
__global__ __launch_bounds__(256) void wfd_k(const float* __restrict__ w,
    bf16* __restrict__ h, bf16* __restrict__ l)
{
    size_t total = (size_t)16384*512;
    for (size_t i = blockIdx.x*(size_t)blockDim.x + threadIdx.x; i < total;
         i += (size_t)gridDim.x*blockDim.x){
        int fp = (int)(i >> 9), e = (int)(i & 511);
        int t = fp >> 9, c = fp & 511;
        float v = w[((size_t)(c*32 + t))*512 + e];
        bf16 hh, ll; split2(v, hh, ll); h[i] = hh; l[i] = ll;
    }
}
__global__ __launch_bounds__(256) void dfb2_k(const float* __restrict__ b,
    float* __restrict__ b2)
{
    int i = blockIdx.x*blockDim.x + threadIdx.x;
    int t = i >> 9, c = i & 511;
    b2[i] = b[c*32 + t];
}
__global__ __launch_bounds__(256) void plainsplit_k(const float* __restrict__ s,
    bf16* __restrict__ h, bf16* __restrict__ l, size_t n)
{
    for (size_t i = blockIdx.x*(size_t)blockDim.x + threadIdx.x; i < n;
         i += (size_t)gridDim.x*blockDim.x){
        bf16 hh, ll; split2(s[i], hh, ll); h[i] = hh; l[i] = ll;
    }
}
__global__ __launch_bounds__(256) void xsplit_k(const float* __restrict__ x,
    bf16* __restrict__ h, bf16* __restrict__ l)
{
    size_t total = (size_t)BB*CIN*TT;
    for (size_t i = blockIdx.x*(size_t)blockDim.x + threadIdx.x; i < total;
         i += (size_t)gridDim.x*blockDim.x){
        int b = (int)(i >> 13), r = (int)(i & 8191);
        int c = r >> 5, t = r & 31;
        size_t d = (size_t)(b*32 + t)*256 + c;
        bf16 hh, ll; split2(x[i], hh, ll); h[d] = hh; l[d] = ll;
    }
}
__global__ __launch_bounds__(256) void reducez_k(const float* __restrict__ part,
    const float* __restrict__ efb, float* __restrict__ z,
    bf16* __restrict__ zh, bf16* __restrict__ zl)
{
    int i = blockIdx.x*blockDim.x + threadIdx.x;   // 524288
    int e = i & 511;
    float s = 0.f;
    #pragma unroll
    for (int k = 0; k < 8; k++) s += part[(size_t)k*524288 + i];
    s += efb[e];
    z[i] = s;
    bf16 hh, ll; split2(s, hh, ll); zh[i] = hh; zl[i] = ll;
}
__global__ __launch_bounds__(256) void cnorm_k(const float* __restrict__ cb,
                                               float* __restrict__ cn)
{
    int n = blockIdx.x*8 + (threadIdx.x >> 5);
    int lane = threadIdx.x & 31;
    const float* r = cb + (size_t)n*EE;
    float s = 0.f;
    for (int e = lane; e < EE; e += 32){ float v = r[e]; s += v*v; }
    #pragma unroll
    for (int o = 16; o; o >>= 1) s += __shfl_down_sync(0xffffffffu, s, o);
    if (lane == 0) cn[n] = s;
}
__global__ __launch_bounds__(256) void vq_k(
    const float* __restrict__ z, const float* __restrict__ dot,
    const float* __restrict__ cn, const float* __restrict__ cb,
    bf16* __restrict__ zqh, bf16* __restrict__ zql, float* __restrict__ lp)
{
    __shared__ float sv[256];
    __shared__ int   si[256];
    __shared__ float s_zn;
    const int b = blockIdx.x, tid = threadIdx.x;
    const float* zb = z + (size_t)b*EE;

    float zn = 0.f;
    for (int e = tid; e < EE; e += 256){ float v = zb[e]; zn += v*v; }
    sv[tid] = zn; __syncthreads();
    for (int s = 128; s > 0; s >>= 1){ if (tid < s) sv[tid] += sv[tid+s]; __syncthreads(); }
    if (tid == 0) s_zn = sv[0];
    __syncthreads();
    zn = s_zn; __syncthreads();

    const float* db = dot + (size_t)b*NEC;
    float best = 3.4e38f; int bi = 0x7fffffff;
    for (int n = tid; n < NEC; n += 256){
        float dv = (zn + cn[n]) - 2.0f * db[n];
        if (dv < best || (dv == best && n < bi)){ best = dv; bi = n; }
    }
    sv[tid] = best; si[tid] = bi; __syncthreads();
    for (int s = 128; s > 0; s >>= 1){
        if (tid < s){
            float v2 = sv[tid+s]; int i2 = si[tid+s];
            if (v2 < sv[tid] || (v2 == sv[tid] && i2 < si[tid])){ sv[tid] = v2; si[tid] = i2; }
        }
        __syncthreads();
    }
    const int idx = si[0];
    __syncthreads();

    const float* cbr = cb + (size_t)idx*EE;
    float ls = 0.f;
    for (int e = tid; e < EE; e += 256){
        float q = cbr[e];
        bf16 hh, ll; split2(q, hh, ll);
        zqh[(size_t)b*EE + e] = hh; zql[(size_t)b*EE + e] = ll;
        float d = q - zb[e]; ls += d*d;
    }
    sv[tid] = ls; __syncthreads();
    for (int s = 128; s > 0; s >>= 1){ if (tid < s) sv[tid] += sv[tid+s]; __syncthreads(); }
    if (tid == 0) lp[b] = sv[0];
}
__global__ __launch_bounds__(256) void loss_final_k(const float* __restrict__ lp,
                                                    float* __restrict__ outLoss)
{
    __shared__ float sm[256];
    int tid = threadIdx.x;
    float s = 0.f;
    #pragma unroll
    for (int i = 0; i < 4; i++) s += lp[tid + i*256];
    sm[tid] = s; __syncthreads();
    for (int st = 128; st > 0; st >>= 1){ if (tid < st) sm[tid] += sm[tid+st]; __syncthreads(); }
    if (tid == 0) *outLoss = sm[0] * 1.25f / ((float)BB * (float)EE);
}

// =====================================================================
#define SYM(p, s) do{ void* _t; cudaGetSymbolAddress(&_t, s); p = (decltype(p))_t; }while(0)

extern "C" void kernel_launch(void* const* d_in, const int* in_sizes, int n_in,
                              void* d_out, int out_size)
{
    const float* x   = (const float*)d_in[0];
    const float* ew1 = (const float*)d_in[1];  const float* eb1 = (const float*)d_in[2];
    const float* ew2 = (const float*)d_in[3];  const float* eb2 = (const float*)d_in[4];
    const float* ew3 = (const float*)d_in[5];  const float* eb3 = (const float*)d_in[6];
    const float* ew4 = (const float*)d_in[7];  const float* eb4 = (const float*)d_in[8];
    const float* efw = (const float*)d_in[9];  const float* efb = (const float*)d_in[10];
    const float* cb  = (const float*)d_in[11];
    const float* dfw = (const float*)d_in[12]; const float* dfb = (const float*)d_in[13];
    const float* dw4 = (const float*)d_in[14]; const float* db4 = (const float*)d_in[15];
    const float* dw3 = (const float*)d_in[16]; const float* db3 = (const float*)d_in[17];
    const float* dw2 = (const float*)d_in[18]; const float* db2 = (const float*)d_in[19];
    const float* dw1 = (const float*)d_in[20]; const float* db1 = (const float*)d_in[21];
    float* out = (float*)d_out;

    bf16 *aAh,*aAl,*aBh,*aBl;
    bf16 *w1h,*w1l,*w2h,*w2l,*w3h,*w3l,*w4h,*w4l;
    bf16 *d4h,*d4l,*d3h,*d3l,*d2h,*d2l,*d1h,*d1l;
    bf16 *feh,*fel,*fdh,*fdl,*cbh,*cbl,*zh,*zl,*zqh,*zql;
    float *part,*z,*dot,*cn,*lp,*dfb2;
    SYM(aAh,g_actAh); SYM(aAl,g_actAl); SYM(aBh,g_actBh); SYM(aBl,g_actBl);
    SYM(w1h,g_wA1h); SYM(w1l,g_wA1l); SYM(w2h,g_wA2h); SYM(w2l,g_wA2l);
    SYM(w3h,g_wA3h); SYM(w3l,g_wA3l); SYM(w4h,g_wA4h); SYM(w4l,g_wA4l);
    SYM(d4h,g_wD4h); SYM(d4l,g_wD4l); SYM(d3h,g_wD3h); SYM(d3l,g_wD3l);
    SYM(d2h,g_wD2h); SYM(d2l,g_wD2l); SYM(d1h,g_wD1h); SYM(d1l,g_wD1l);
    SYM(feh,g_wFEh); SYM(fel,g_wFEl); SYM(fdh,g_wFDh); SYM(fdl,g_wFDl);
    SYM(cbh,g_cbh);  SYM(cbl,g_cbl);
    SYM(zh,g_zh); SYM(zl,g_zl); SYM(zqh,g_zqh); SYM(zql,g_zql);
    SYM(part,g_part); SYM(z,g_z); SYM(dot,g_dot); SYM(cn,g_cn); SYM(lp,g_lp);
    SYM(dfb2,g_dfb2);

    cudaFuncSetAttribute(gemm_mma, cudaFuncAttributeMaxDynamicSharedMemorySize, GS);

    // ---- transforms ----
    xsplit_k<<<1024, 256>>>(x, aAh, aAl);
    wconv_k<<<512, 256>>>(ew1, w1h, w1l, 512, 256, 0);
    wconv_k<<<512, 256>>>(ew2, w2h, w2l, 512, 512, 0);
    wconv_k<<<512, 256>>>(ew3, w3h, w3l, 512, 512, 0);
    wconv_k<<<512, 256>>>(ew4, w4h, w4l, 512, 512, 0);
    wfe_k<<<2048, 256>>>(efw, feh, fel);
    plainsplit_k<<<2048, 256>>>(cb, cbh, cbl, (size_t)NEC*EE);
    cnorm_k<<<NEC/8, 256>>>(cb, cn);
    wfd_k<<<2048, 256>>>(dfw, fdh, fdl);
    dfb2_k<<<64, 256>>>(dfb, dfb2);
    wconv_k<<<512, 256>>>(dw4, d4h, d4l, 512, 512, 1);
    wconv_k<<<512, 256>>>(dw3, d3h, d3l, 512, 512, 1);
    wconv_k<<<512, 256>>>(dw2, d2h, d2l, 512, 512, 1);
    wconv_k<<<512, 256>>>(dw1, d1h, d1l, 256, 512, 1);

    // ---- encoder convs ----
    gemm_mma<<<dim3(NNC/128, 4, 1), 256, GS>>>(w1h, w1l, aAh, aAl, eb1,
        nullptr, aBh, aBl, nullptr, 512, 768,  768,  256, 0, 0, 1);
    gemm_mma<<<dim3(NNC/128, 4, 1), 256, GS>>>(w2h, w2l, aBh, aBl, eb2,
        nullptr, aAh, aAl, nullptr, 512, 1536, 1536, 512, 0, 0, 1);
    gemm_mma<<<dim3(NNC/128, 4, 1), 256, GS>>>(w3h, w3l, aAh, aAl, eb3,
        nullptr, aBh, aBl, nullptr, 512, 1536, 1536, 512, 0, 0, 1);
    gemm_mma<<<dim3(NNC/128, 4, 1), 256, GS>>>(w4h, w4l, aBh, aBl, eb4,
        nullptr, aAh, aAl, nullptr, 512, 1536, 1536, 512, 0, 0, 1);

    // ---- encoder FC: M=512, N=1024, K=16384, split-K=8 ----
    gemm_mma<<<dim3(BB/128, 4, 8), 256, GS>>>(feh, fel, aAh, aAl, nullptr,
        nullptr, nullptr, nullptr, part, 512, 16384, 2048, 0, 0, 0, 0);
    reducez_k<<<2048, 256>>>(part, efb, z, zh, zl);

    // ---- VQ: dot = z @ cb^T ----
    gemm_mma<<<dim3(BB/128, NEC/128, 1), 256, GS>>>(cbh, cbl, zh, zl, nullptr,
        dot, nullptr, nullptr, nullptr, NEC, EE, EE, 0, 1, NEC, 0);
    vq_k<<<BB, 256>>>(z, dot, cn, cb, zqh, zql, lp);

    // ---- decoder FC: M=16384, N=1024, K=512 ----
    gemm_mma<<<dim3(BB/128, 16384/128, 1), 256, GS>>>(fdh, fdl, zqh, zql, dfb2,
        nullptr, aBh, aBl, nullptr, 16384, EE, EE, 0, 0, 0, 0);

    // ---- decoder convs ----
    gemm_mma<<<dim3(NNC/128, 4, 1), 256, GS>>>(d4h, d4l, aBh, aBl, db4,
        nullptr, aAh, aAl, nullptr, 512, 1536, 1536, 512, 0, 0, 1);
    gemm_mma<<<dim3(NNC/128, 4, 1), 256, GS>>>(d3h, d3l, aAh, aAl, db3,
        nullptr, aBh, aBl, nullptr, 512, 1536, 1536, 512, 0, 0, 1);
    gemm_mma<<<dim3(NNC/128, 4, 1), 256, GS>>>(d2h, d2l, aBh, aBl, db2,
        nullptr, aAh, aAl, nullptr, 512, 1536, 1536, 512, 0, 0, 1);
    gemm_mma<<<dim3(NNC/128, 2, 1), 256, GS>>>(d1h, d1l, aAh, aAl, db1,
        out, nullptr, nullptr, nullptr, 256, 1536, 1536, 512, 2, 0, 0);

    if (out_size >= RECON_N + 1)
        loss_final_k<<<1, 256>>>(lp, out + RECON_N);
}